// round 13
// baseline (speedup 1.0000x reference)
#include <cuda_runtime.h>

#define T_SEQ   2048
#define BATCH   64
#define INP     16
#define HEADS   8
#define HID     64
#define GATES   256
#define BC      2
#define NTHREADS 256
#define OUT_ELEMS  (T_SEQ * BATCH * HEADS)
#define LOUT_ELEMS (T_SEQ * BATCH * HID)

// Packed fp32x2 FMA (sm_100+): 2 MACs/instr, 2x FFMA throughput.
__device__ __forceinline__ float2 ffma2(float2 a, float2 b, float2 c) {
    float2 d;
    asm("fma.rn.f32x2 %0, %1, %2, %3;"
        : "=l"(reinterpret_cast<unsigned long long&>(d))
        : "l"(reinterpret_cast<const unsigned long long&>(a)),
          "l"(reinterpret_cast<const unsigned long long&>(b)),
          "l"(reinterpret_cast<const unsigned long long&>(c)));
    return d;
}

__device__ __forceinline__ float fsig(float x) {
    return __fdividef(1.0f, 1.0f + __expf(-x));
}
__device__ __forceinline__ float ftanh_(float x) {
    return fmaf(2.0f, fsig(2.0f * x), -1.0f);
}

// CTA = (head, 2 batches), 256 threads, occ 2 (two independent chains/SM).
//
// Row mapping puts all 4 gates of a hidden unit in ONE warp:
//   warp w owns d in [8w, 8w+8); lane l = g3*8 + dl -> row = g3*64 + 8w + dl.
// Step: full-k z in-thread -> local activation (tanh for g-rows, sigmoid
// else) -> 4 shfl.idx gathers the 4 activated gates of (d = 8w+dl) -> every
// lane updates c,h for its d (4-way duplicated across g3 groups; per-warp
// instruction count is unchanged). The duplicate groups split the output
// jobs: g3=0 stores h to smem, g3=1 drains lout, g3=2/3 drain out.
// ONE __syncthreads per step, no zb staging array at all.
__global__ void __launch_bounds__(NTHREADS, 2)
lstm_kernel(const float* __restrict__ x,    const float* __restrict__ Wih,
            const float* __restrict__ Whh,  const float* __restrict__ bih,
            const float* __restrict__ bhh,  const float* __restrict__ Wlin,
            const float* __restrict__ blin, float* __restrict__ out,
            float* __restrict__ lout)
{
    const int h   = blockIdx.x >> 5;           // head 0..7
    const int b0  = (blockIdx.x & 31) * BC;    // first batch of this CTA
    const int j   = threadIdx.x;
    const int w   = j >> 5;                    // warp 0..7
    const int l   = j & 31;
    const int g3  = l >> 3;                    // gate 0:i 1:f 2:g 3:o
    const int dl  = l & 7;
    const int dm  = w * 8 + dl;                // this lane's hidden unit
    const int row = g3 * HID + dm;             // gate row this thread computes

    __shared__ __align__(16) float hs[2][BC * HID];  // [buf][b*64+d]
    __shared__ __align__(16) float xs[2][BC * INP];  // x double buffer

    // ---- weights -> registers (row) ----
    float2 w2[HID / 2];
    {
        const float4* wr = reinterpret_cast<const float4*>(Whh + (size_t)(h * GATES + row) * HID);
#pragma unroll
        for (int q = 0; q < HID / 4; ++q) {
            float4 v = wr[q];
            w2[2 * q]     = make_float2(v.x, v.y);
            w2[2 * q + 1] = make_float2(v.z, v.w);
        }
    }
    float2 wi2[INP / 2];
    {
        const float4* wr = reinterpret_cast<const float4*>(Wih + (size_t)(h * GATES + row) * INP);
#pragma unroll
        for (int q = 0; q < INP / 4; ++q) {
            float4 v = wr[q];
            wi2[2 * q]     = make_float2(v.x, v.y);
            wi2[2 * q + 1] = make_float2(v.z, v.w);
        }
    }
    const float bias     = bih[h * GATES + row] + bhh[h * GATES + row];
    const float wlin_d   = Wlin[h * HID + dm];
    const float blin_add = (dm == 0) ? blin[h] : 0.0f;   // counted once per (t,b)

    // ---- init ----
    if (j < BC * HID) hs[0][j] = 0.0f;
    float c0 = 0.0f, c1 = 0.0f;
    float xreg = 0.0f;
    if (j < BC * INP) {
        xs[0][j] = x[(size_t)0 * BATCH * INP + b0 * INP + j];
        xreg     = x[(size_t)1 * BATCH * INP + b0 * INP + j];
    }
    __syncthreads();

    for (int t = 0; t < T_SEQ; ++t) {
        const float* hb = hs[t & 1];
        const float* xb = xs[t & 1];

        // ---- z for this gate row, both batches (full k in-thread) ----
        float z0, z1;
        {
            float2 a0 = make_float2(bias, 0.0f), a1 = make_float2(0.0f, 0.0f);
            float2 b0a = make_float2(bias, 0.0f), b1a = make_float2(0.0f, 0.0f);
            const float4* hv0 = reinterpret_cast<const float4*>(hb);
            const float4* hv1 = reinterpret_cast<const float4*>(hb + HID);
#pragma unroll
            for (int q = 0; q < HID / 4; ++q) {
                float4 v0 = hv0[q], v1 = hv1[q];
                a0  = ffma2(w2[2 * q],     make_float2(v0.x, v0.y), a0);
                a1  = ffma2(w2[2 * q + 1], make_float2(v0.z, v0.w), a1);
                b0a = ffma2(w2[2 * q],     make_float2(v1.x, v1.y), b0a);
                b1a = ffma2(w2[2 * q + 1], make_float2(v1.z, v1.w), b1a);
            }
            const float4* xv0 = reinterpret_cast<const float4*>(xb);
            const float4* xv1 = reinterpret_cast<const float4*>(xb + INP);
#pragma unroll
            for (int q = 0; q < INP / 4; ++q) {
                float4 v0 = xv0[q], v1 = xv1[q];
                a0  = ffma2(wi2[2 * q],     make_float2(v0.x, v0.y), a0);
                a1  = ffma2(wi2[2 * q + 1], make_float2(v0.z, v0.w), a1);
                b0a = ffma2(wi2[2 * q],     make_float2(v1.x, v1.y), b0a);
                b1a = ffma2(wi2[2 * q + 1], make_float2(v1.z, v1.w), b1a);
            }
            z0 = (a0.x + a0.y) + (a1.x + a1.y);
            z1 = (b0a.x + b0a.y) + (b1a.x + b1a.y);
        }

        // ---- local activation of own gate row ----
        float za0, za1;
        if (g3 == 2) { za0 = ftanh_(z0); za1 = ftanh_(z1); }
        else         { za0 = fsig(z0);   za1 = fsig(z1);   }

        // ---- gather the 4 activated gates of (d = 8w+dl) via shfl.idx ----
        float gi0 = __shfl_sync(0xffffffffu, za0,      dl);
        float gf0 = __shfl_sync(0xffffffffu, za0,  8 + dl);
        float gg0 = __shfl_sync(0xffffffffu, za0, 16 + dl);
        float go0 = __shfl_sync(0xffffffffu, za0, 24 + dl);
        float gi1 = __shfl_sync(0xffffffffu, za1,      dl);
        float gf1 = __shfl_sync(0xffffffffu, za1,  8 + dl);
        float gg1 = __shfl_sync(0xffffffffu, za1, 16 + dl);
        float go1 = __shfl_sync(0xffffffffu, za1, 24 + dl);

        // ---- state update (duplicated across the 4 g3 groups, identical) ----
        c0 = fmaf(gf0, c0, gi0 * gg0);
        c1 = fmaf(gf1, c1, gi1 * gg1);
        float h0 = go0 * ftanh_(c0);
        float h1 = go1 * ftanh_(c1);

        // ---- output jobs split across the duplicate groups ----
        if (g3 == 0) {
            hs[(t + 1) & 1][dm]       = h0;
            hs[(t + 1) & 1][HID + dm] = h1;
        }
        if (g3 == 1) {
            atomicAdd(lout + (size_t)(t * BATCH + b0)     * HID + dm, h0);
            atomicAdd(lout + (size_t)(t * BATCH + b0 + 1) * HID + dm, h1);
        }
        if (g3 == 2)
            atomicAdd(out + (size_t)(t * BATCH + b0)     * HEADS + h, fmaf(h0, wlin_d, blin_add));
        if (g3 == 3)
            atomicAdd(out + (size_t)(t * BATCH + b0 + 1) * HEADS + h, fmaf(h1, wlin_d, blin_add));

        // x pipeline: publish x_{t+1} (loaded a step ago), prefetch x_{t+2}
        if (j < BC * INP) {
            if (t + 1 < T_SEQ) xs[(t + 1) & 1][j] = xreg;
            if (t + 2 < T_SEQ) xreg = x[(size_t)(t + 2) * BATCH * INP + b0 * INP + j];
        }
        __syncthreads();
    }
}

extern "C" void kernel_launch(void* const* d_in, const int* in_sizes, int n_in,
                              void* d_out, int out_size) {
    const float* x    = (const float*)d_in[0];
    const float* Wih  = (const float*)d_in[1];
    const float* Whh  = (const float*)d_in[2];
    const float* bih  = (const float*)d_in[3];
    const float* bhh  = (const float*)d_in[4];
    const float* Wlin = (const float*)d_in[5];
    const float* blin = (const float*)d_in[6];

    float* out  = (float*)d_out;                 // (T,B,H), atomic-accumulated
    float* lout = out + OUT_ELEMS;               // (T,B,HID), atomic-accumulated

    // both regions are accumulated with REDs -> zero the whole output
    cudaMemsetAsync(d_out, 0, (size_t)(OUT_ELEMS + LOUT_ELEMS) * sizeof(float), 0);

    lstm_kernel<<<HEADS * (BATCH / BC), NTHREADS>>>(
        x, Wih, Whh, bih, bhh, Wlin, blin, out, lout);
}